// round 17
// baseline (speedup 1.0000x reference)
#include <cuda_runtime.h>

// db4 single-level 2D DWT, circular padding (end), stride-2 cross-correlation.
// x: (96, 512, 512) f32 -> out: (96*4, 256, 256) f32, subband order ll,lh,hl,hh.
//
// Column pass FIRST (full-width stripes) with packed f32x2 FMA over adjacent
// column pairs (loaded u64 IS the operand). Each block processes TWO stripes
// with double-buffered planes; stripe-1's load-bound column pass is issued
// back-to-back with stripe-0's smem/FMA-bound row pass (no barrier between),
// so LDG latency hides under row-pass compute.

#define HH   512
#define WW   512
#define OWW  256
#define TH   8             // output rows per stripe
#define IN_R (2*TH + 6)    // 22 input rows per stripe
#define PW   520           // plane width: 512 + 8 wrap-halo cols
#define NT   256           // threads per block (thread owns 2 columns)
#define PLANE (TH * PW)    // floats per plane
#define BUFSZ (2 * PLANE)  // lo+hi planes per stripe buffer
#define SMEM_BYTES (2 * BUFSZ * 4)

typedef unsigned long long u64;

static __device__ __forceinline__ u64 pk(float a, float b) {
    u64 r; asm("mov.b64 %0, {%1, %2};" : "=l"(r) : "f"(a), "f"(b)); return r;
}
static __device__ __forceinline__ void fma2(u64& d, u64 a, u64 b) {
    asm("fma.rn.f32x2 %0, %1, %2, %0;" : "+l"(d) : "l"(a), "l"(b));
}
static __device__ __forceinline__ void mul2(u64& d, u64 a, u64 b) {
    asm("mul.rn.f32x2 %0, %1, %2;" : "=l"(d) : "l"(a), "l"(b));
}

__global__ __launch_bounds__(NT, 3) void dwt2d_db4_kernel(
    const float* __restrict__ x,
    float* __restrict__ out)
{
    extern __shared__ float sm[];   // [2 buffers][lo plane | hi plane]

    const float FL[8] = {-0.010597401784997278f,  0.032883011666982945f,
                          0.030841381835986965f, -0.18703481171888114f,
                         -0.02798376941698385f,   0.6308807679295904f,
                          0.7148465705525415f,    0.23037781330885523f};
    const float FH[8] = {-0.23037781330885523f,   0.7148465705525415f,
                         -0.6308807679295904f,   -0.02798376941698385f,
                          0.18703481171888114f,   0.030841381835986965f,
                         -0.032883011666982945f, -0.010597401784997278f};

    // dup coefficient pairs for the packed column pass
    u64 CLd[8], CHd[8];
    #pragma unroll
    for (int t = 0; t < 8; t++) {
        CLd[t] = pk(FL[t], FL[t]);
        CHd[t] = pk(FH[t], FH[t]);
    }

    const int tid  = threadIdx.x;         // 0..255
    const int img  = blockIdx.y;          // 0..95
    const int h0a  = blockIdx.x * 2 * TH; // stripe 0 output row base
    const int h0b  = h0a + TH;            // stripe 1 output row base

    const float* __restrict__ xin  = x   + (size_t)img * HH * WW;
    float*       __restrict__ outi = out + (size_t)img * 4 * OWW * OWW;
    const size_t SB = (size_t)OWW * OWW;

    // ---- column pass for one stripe (packed FFMA2 over adjacent col pair) ----
    auto phaseA = [&](int h0, float* __restrict__ sLo, float* __restrict__ sHi) {
        const int r0 = 2 * h0;
        u64 aLo[4], aHi[4];                // ring over j&3
        #pragma unroll
        for (int k = 0; k < IN_R; k++) {
            int gr = (r0 + k) & (HH - 1);
            u64 v = *(const u64*)(xin + (size_t)gr * WW + 2 * tid);
            #pragma unroll
            for (int j = 0; j < TH; j++) {
                const int t = k - 2 * j;
                if (t == 0) {
                    mul2(aLo[j & 3], CLd[0], v);
                    mul2(aHi[j & 3], CHd[0], v);
                } else if (t > 0 && t < 8) {
                    fma2(aLo[j & 3], CLd[t], v);
                    fma2(aHi[j & 3], CHd[t], v);
                }
                if (t == 7) {
                    *(u64*)&sLo[j * PW + 2 * tid] = aLo[j & 3];
                    *(u64*)&sHi[j * PW + 2 * tid] = aHi[j & 3];
                    if (tid < 4) {                  // wrap halo cols 512..519
                        *(u64*)&sLo[j * PW + WW + 2 * tid] = aLo[j & 3];
                        *(u64*)&sHi[j * PW + WW + 2 * tid] = aHi[j & 3];
                    }
                }
            }
        }
    };

    // ---- row pass for one stripe (scalar FMA, coef immediates) ----
    auto phaseB = [&](int h0, const float* __restrict__ sLo,
                              const float* __restrict__ sHi) {
        #pragma unroll
        for (int it = 0; it < 8; it++) {
            int idx = tid + it * NT;             // 0..2047
            int wp  = idx & 127;                 // col-pair index
            int j   = (idx >> 7) & (TH - 1);     // 0..7
            int pl  = idx >> 10;                 // 0..1
            const float* __restrict__ A = (pl ? sHi : sLo) + j * PW;

            float4 q0 = *(const float4*)(A + 4 * wp);
            float4 q1 = *(const float4*)(A + 4 * wp + 4);
            float2 q2 = *(const float2*)(A + 4 * wp + 8);
            float v[10] = {q0.x, q0.y, q0.z, q0.w,
                           q1.x, q1.y, q1.z, q1.w,
                           q2.x, q2.y};

            float lo0 = 0.f, hi0 = 0.f, lo1 = 0.f, hi1 = 0.f;
            #pragma unroll
            for (int t = 0; t < 8; t++) {
                lo0 = fmaf(FL[t], v[t],     lo0);
                hi0 = fmaf(FH[t], v[t],     hi0);
                lo1 = fmaf(FL[t], v[t + 2], lo1);
                hi1 = fmaf(FH[t], v[t + 2], hi1);
            }

            int sbL = pl ? 1 : 0;
            int sbH = pl ? 3 : 2;
            size_t o = (size_t)(h0 + j) * OWW + 2 * wp;
            *(float2*)(outi + sbL * SB + o) = make_float2(lo0, lo1);
            *(float2*)(outi + sbH * SB + o) = make_float2(hi0, hi1);
        }
    };

    float* lo0p = sm;
    float* hi0p = sm + PLANE;
    float* lo1p = sm + BUFSZ;
    float* hi1p = sm + BUFSZ + PLANE;

    phaseA(h0a, lo0p, hi0p);
    __syncthreads();
    // stripe-1 loads overlap stripe-0 row pass (disjoint buffers, no barrier)
    phaseA(h0b, lo1p, hi1p);
    phaseB(h0a, lo0p, hi0p);
    __syncthreads();
    phaseB(h0b, lo1p, hi1p);
}

extern "C" void kernel_launch(void* const* d_in, const int* in_sizes, int n_in,
                              void* d_out, int out_size)
{
    const float* x = (const float*)d_in[0];   // (32,3,512,512) f32
    float* out = (float*)d_out;               // (32,12,256,256) f32

    cudaFuncSetAttribute(dwt2d_db4_kernel,
                         cudaFuncAttributeMaxDynamicSharedMemorySize, SMEM_BYTES);
    dim3 grid(OWW / (2 * TH), 96);            // (16 stripe-pairs, 96 images)
    dwt2d_db4_kernel<<<grid, NT, SMEM_BYTES>>>(x, out);
}